// round 1
// baseline (speedup 1.0000x reference)
#include <cuda_runtime.h>

#define BD   8
#define SD   512
#define PD   8
#define DIN  768
#define DM   1024
#define NPOS (BD*SD)          /* 4096 rows */
#define EPSL 1e-5f

#define BM 128
#define BN 128
#define BK 8
#define TM 8
#define TN 8

// Scratch (static device memory — no allocations in kernel_launch)
__device__ float g_pooled[(size_t)NPOS * DIN];   // 12.6 MB
__device__ float g_emb[(size_t)NPOS * DM];       // 16.8 MB

// ---------------------------------------------------------------------------
// Kernel 1: masked mean-pool over P param vectors.
// pooled[pos, :] = (1/max(n,1)) * sum_{p<n} pv[pos, p, :]
// One block per (b,s) position; 192 threads, each owns one float4 column chunk
// (768 f32 = 192 float4).
// ---------------------------------------------------------------------------
__global__ __launch_bounds__(192) void pool_kernel(const float* __restrict__ pv,
                                                   const int* __restrict__ np) {
    int pos = blockIdx.x;
    int n = np[pos];
    float inv = (n > 0) ? 1.0f / (float)n : 0.0f;
    const float4* base = (const float4*)(pv + (size_t)pos * PD * DIN);
    float4* out = (float4*)(g_pooled + (size_t)pos * DIN);
    int c = threadIdx.x;                       // 0..191
    float4 acc = make_float4(0.f, 0.f, 0.f, 0.f);
    for (int p = 0; p < n; ++p) {
        float4 v = base[p * (DIN / 4) + c];
        acc.x += v.x; acc.y += v.y; acc.z += v.z; acc.w += v.w;
    }
    out[c] = make_float4(acc.x * inv, acc.y * inv, acc.z * inv, acc.w * inv);
}

// ---------------------------------------------------------------------------
// Kernel 2: SGEMM g_emb = g_pooled[4096,768] @ W[768,1024]  (no bias here).
// Classic 128x128x8 shared-memory tiling, 8x8 register microtile, 256 threads.
// All dims divide the tile sizes exactly — no bounds checks.
// ---------------------------------------------------------------------------
__global__ __launch_bounds__(256) void gemm_kernel(const float* __restrict__ W) {
    __shared__ float As[BK][BM];   // A stored transposed: As[k][m]
    __shared__ float Bs[BK][BN];

    int tid = threadIdx.x;
    int bm = blockIdx.y * BM;
    int bn = blockIdx.x * BN;

    int ty = tid / 16;             // 0..15 -> row group (8 rows each)
    int tx = tid % 16;             // 0..15 -> col group (8 cols each)

    // A-tile loader mapping: 128 rows x 8 k = 256 float4
    int a_row = tid >> 1;          // 0..127
    int a_kk  = (tid & 1) * 4;     // 0 or 4
    // B-tile loader mapping: 8 k x 128 n = 256 float4
    int b_k = tid >> 5;            // 0..7
    int b_n = (tid & 31) * 4;      // 0..124

    float acc[TM][TN];
    #pragma unroll
    for (int i = 0; i < TM; i++)
        #pragma unroll
        for (int j = 0; j < TN; j++) acc[i][j] = 0.f;

    const float* A = g_pooled;

    for (int k0 = 0; k0 < DIN; k0 += BK) {
        float4 av = *(const float4*)(A + (size_t)(bm + a_row) * DIN + k0 + a_kk);
        float4 bv = *(const float4*)(W + (size_t)(k0 + b_k) * DM + bn + b_n);
        As[a_kk + 0][a_row] = av.x;
        As[a_kk + 1][a_row] = av.y;
        As[a_kk + 2][a_row] = av.z;
        As[a_kk + 3][a_row] = av.w;
        *(float4*)&Bs[b_k][b_n] = bv;
        __syncthreads();

        #pragma unroll
        for (int k = 0; k < BK; ++k) {
            float af[TM], bf[TN];
            #pragma unroll
            for (int i = 0; i < TM; i++) af[i] = As[k][ty * TM + i];
            #pragma unroll
            for (int j = 0; j < TN; j++) bf[j] = Bs[k][tx * TN + j];
            #pragma unroll
            for (int i = 0; i < TM; i++)
                #pragma unroll
                for (int j = 0; j < TN; j++) acc[i][j] += af[i] * bf[j];
        }
        __syncthreads();
    }

    #pragma unroll
    for (int i = 0; i < TM; i++) {
        float* o = g_emb + (size_t)(bm + ty * TM + i) * DM + bn + tx * TN;
        #pragma unroll
        for (int j = 0; j < TN; j += 4)
            *(float4*)(o + j) = make_float4(acc[i][j], acc[i][j + 1],
                                            acc[i][j + 2], acc[i][j + 3]);
    }
}

// ---------------------------------------------------------------------------
// Kernel 3: bias (gated on n>0) + LayerNorm over DM=1024, write final output.
// One block per row; 256 threads, each owns one float4 (1024 = 256*4).
// ---------------------------------------------------------------------------
__global__ __launch_bounds__(256) void ln_kernel(const int* __restrict__ np,
                                                 const float* __restrict__ bias,
                                                 const float* __restrict__ gamma,
                                                 const float* __restrict__ beta,
                                                 float* __restrict__ out) {
    int row = blockIdx.x;
    int t = threadIdx.x;
    float bscale = (np[row] > 0) ? 1.0f : 0.0f;

    float4 x = ((const float4*)(g_emb + (size_t)row * DM))[t];
    float4 bb = ((const float4*)bias)[t];
    x.x += bscale * bb.x; x.y += bscale * bb.y;
    x.z += bscale * bb.z; x.w += bscale * bb.w;

    float s  = x.x + x.y + x.z + x.w;
    float sq = x.x * x.x + x.y * x.y + x.z * x.z + x.w * x.w;

    #pragma unroll
    for (int o = 16; o > 0; o >>= 1) {
        s  += __shfl_xor_sync(0xffffffffu, s, o);
        sq += __shfl_xor_sync(0xffffffffu, sq, o);
    }

    __shared__ float red_s[8], red_q[8];
    int warp = t >> 5, lane = t & 31;
    if (lane == 0) { red_s[warp] = s; red_q[warp] = sq; }
    __syncthreads();

    s = 0.f; sq = 0.f;
    #pragma unroll
    for (int w = 0; w < 8; ++w) { s += red_s[w]; sq += red_q[w]; }

    float mean = s * (1.0f / DM);
    float var  = sq * (1.0f / DM) - mean * mean;
    float rstd = rsqrtf(var + EPSL);

    float4 g  = ((const float4*)gamma)[t];
    float4 be = ((const float4*)beta)[t];
    float4 o;
    o.x = (x.x - mean) * rstd * g.x + be.x;
    o.y = (x.y - mean) * rstd * g.y + be.y;
    o.z = (x.z - mean) * rstd * g.z + be.z;
    o.w = (x.w - mean) * rstd * g.w + be.w;
    ((float4*)out)[(size_t)row * (DM / 4) + t] = o;
}

// ---------------------------------------------------------------------------
extern "C" void kernel_launch(void* const* d_in, const int* in_sizes, int n_in,
                              void* d_out, int out_size) {
    const float* pv    = (const float*)d_in[0];  // [B,S,P,768]
    const int*   np    = (const int*)d_in[1];    // [B,S]
    const float* W     = (const float*)d_in[2];  // [768,1024]
    const float* bias  = (const float*)d_in[3];  // [1024]
    const float* gamma = (const float*)d_in[4];  // [1024]
    const float* beta  = (const float*)d_in[5];  // [1024]
    float* out = (float*)d_out;                  // [B,S,1024]

    pool_kernel<<<NPOS, 192>>>(pv, np);
    dim3 gg(DM / BN, NPOS / BM);                 // (8, 32) = 256 blocks
    gemm_kernel<<<gg, 256>>>(W);
    ln_kernel<<<NPOS, 256>>>(np, bias, gamma, beta, out);
}

// round 5
// speedup vs baseline: 2.5533x; 2.5533x over previous
#include <cuda_runtime.h>
#include <cstdint>

#define BD   8
#define SD   512
#define PD   8
#define DIN  768
#define DM   1024
#define NPOS (BD*SD)
#define EPSL 1e-5f

// ---------------- GEMM tiling ----------------
#define BM 128
#define BN 128
#define BK 32
#define KITERS (DIN/BK)        // 24
// SMEM: per stage  A[128][36] + B[128][36] floats (pad 4 -> conflict-free frags)
#define ROWF   36
#define ROWB   (ROWF*4)        // 144 bytes per row
#define A_BYTES (BM*ROWB)      // 18432
#define STAGE_BYTES (2*A_BYTES)// 36864 (A then B)
#define SMEM_TOTAL (2*STAGE_BYTES) // 73728

// Scratch (static device memory — no allocations anywhere)
__device__ float g_pooled[(size_t)NPOS * DIN];   // 12.6 MB (tf32-rounded)
__device__ float g_Wt[(size_t)DM * DIN];         // 3 MB  (W^T, K-major, tf32-rounded)
__device__ float g_emb[(size_t)NPOS * DM];       // 16.8 MB

__device__ __forceinline__ uint32_t smem_u32(const void* p) {
    uint32_t a;
    asm("{ .reg .u64 t; cvta.to.shared.u64 t, %1; cvt.u32.u64 %0, t; }" : "=r"(a) : "l"(p));
    return a;
}
// Round fp32 bits to nearest tf32 (HW truncates low 13 mantissa bits)
__device__ __forceinline__ float rn_tf32(float v) {
    return __uint_as_float(__float_as_uint(v) + 0x1000u);
}

#define CP16(dst, src) \
    asm volatile("cp.async.cg.shared.global [%0], [%1], 16;" :: "r"(dst), "l"(src))
#define CP_COMMIT() asm volatile("cp.async.commit_group;" ::: "memory")
#define CP_WAIT1()  asm volatile("cp.async.wait_group 1;" ::: "memory")
#define CP_WAIT0()  asm volatile("cp.async.wait_group 0;" ::: "memory")

__device__ __forceinline__ void mma_tf32(float* d, const uint32_t* a, const uint32_t* b) {
    asm volatile("mma.sync.aligned.m16n8k8.row.col.f32.tf32.tf32.f32 "
        "{%0,%1,%2,%3}, {%4,%5,%6,%7}, {%8,%9}, {%0,%1,%2,%3};"
        : "+f"(d[0]), "+f"(d[1]), "+f"(d[2]), "+f"(d[3])
        : "r"(a[0]), "r"(a[1]), "r"(a[2]), "r"(a[3]), "r"(b[0]), "r"(b[1]));
}

// ---------------------------------------------------------------------------
// Kernel 1: masked mean-pool; output pre-rounded to tf32.
// ---------------------------------------------------------------------------
__global__ __launch_bounds__(192) void pool_kernel(const float* __restrict__ pv,
                                                   const int* __restrict__ np) {
    int pos = blockIdx.x;
    int n = np[pos];
    float inv = (n > 0) ? 1.0f / (float)n : 0.0f;
    const float4* base = (const float4*)(pv + (size_t)pos * PD * DIN);
    int c = threadIdx.x;
    float4 a0 = make_float4(0.f, 0.f, 0.f, 0.f);
    float4 a1 = make_float4(0.f, 0.f, 0.f, 0.f);
    int p = 0;
    for (; p + 2 <= n; p += 2) {
        float4 v = base[p * (DIN/4) + c];
        float4 w = base[(p+1) * (DIN/4) + c];
        a0.x += v.x; a0.y += v.y; a0.z += v.z; a0.w += v.w;
        a1.x += w.x; a1.y += w.y; a1.z += w.z; a1.w += w.w;
    }
    if (p < n) {
        float4 v = base[p * (DIN/4) + c];
        a0.x += v.x; a0.y += v.y; a0.z += v.z; a0.w += v.w;
    }
    ((float4*)(g_pooled + (size_t)pos * DIN))[c] =
        make_float4(rn_tf32((a0.x + a1.x) * inv), rn_tf32((a0.y + a1.y) * inv),
                    rn_tf32((a0.z + a1.z) * inv), rn_tf32((a0.w + a1.w) * inv));
}

// ---------------------------------------------------------------------------
// Kernel 2: transpose W [768,1024] -> g_Wt [1024,768], tf32-rounded.
// ---------------------------------------------------------------------------
__global__ __launch_bounds__(256) void transpose_kernel(const float* __restrict__ W) {
    __shared__ float t[32][33];
    int bx = blockIdx.x, by = blockIdx.y;
    int tx = threadIdx.x & 31, ty = threadIdx.x >> 5;   // 32 x 8
    #pragma unroll
    for (int i = 0; i < 32; i += 8)
        t[ty + i][tx] = W[(size_t)(by*32 + ty + i) * DM + bx*32 + tx];
    __syncthreads();
    #pragma unroll
    for (int i = 0; i < 32; i += 8)
        g_Wt[(size_t)(bx*32 + ty + i) * DIN + by*32 + tx] = rn_tf32(t[tx][ty + i]);
}

// ---------------------------------------------------------------------------
// Kernel 3: tf32 mma.sync GEMM  g_emb[4096,1024] = g_pooled @ g_Wt^T
// 128x128x32 tiles, cp.async double-buffer, 8 warps (4x2) of 32x64 warp-tiles.
// ---------------------------------------------------------------------------
__global__ __launch_bounds__(256, 2) void gemm_mma_kernel() {
    extern __shared__ char smem[];
    const uint32_t sb = smem_u32(smem);
    const int tid  = threadIdx.x;
    const int wid  = tid >> 5;
    const int lane = tid & 31;
    const int gID  = lane >> 2;       // 0..7
    const int tig  = lane & 3;        // 0..3
    const int wm   = wid & 3;         // m-group: 32 rows
    const int wn   = wid >> 2;        // n-group: 64 cols
    const int bm   = blockIdx.y * BM;
    const int bn   = blockIdx.x * BN;

    // per-thread GMEM->SMEM mapping: 4 float4 rows apart by 32
    const int r0 = tid >> 3;          // 0..31
    const int c4 = tid & 7;           // 0..7 (k float4 index)
    const float* gA = g_pooled + (size_t)(bm + r0) * DIN + c4 * 4;
    const float* gB = g_Wt    + (size_t)(bn + r0) * DIN + c4 * 4;
    const uint32_t dA = sb + r0 * ROWB + c4 * 16;
    const uint32_t dB = dA + (uint32_t)A_BYTES;

    float acc[2][8][4];
    #pragma unroll
    for (int mi = 0; mi < 2; mi++)
        #pragma unroll
        for (int ni = 0; ni < 8; ni++)
            #pragma unroll
            for (int q = 0; q < 4; q++) acc[mi][ni][q] = 0.f;

    // prologue: stage 0
    #pragma unroll
    for (int j = 0; j < 4; j++) {
        CP16(dA + j * 32 * ROWB, gA + (size_t)(j * 32) * DIN);
        CP16(dB + j * 32 * ROWB, gB + (size_t)(j * 32) * DIN);
    }
    CP_COMMIT();

    #pragma unroll 1
    for (int c = 0; c < KITERS; ++c) {
        if (c + 1 < KITERS) {
            const uint32_t st = ((c + 1) & 1) * STAGE_BYTES;
            const int k0 = (c + 1) * BK;
            #pragma unroll
            for (int j = 0; j < 4; j++) {
                CP16(dA + st + j * 32 * ROWB, gA + (size_t)(j * 32) * DIN + k0);
                CP16(dB + st + j * 32 * ROWB, gB + (size_t)(j * 32) * DIN + k0);
            }
            CP_COMMIT();
            CP_WAIT1();
        } else {
            CP_WAIT0();
        }
        __syncthreads();

        const float* As = (const float*)(smem + (c & 1) * STAGE_BYTES);
        const float* Bs = (const float*)(smem + (c & 1) * STAGE_BYTES + A_BYTES);

        #pragma unroll
        for (int ks = 0; ks < 4; ++ks) {
            const int kk = ks * 8;
            uint32_t af[2][4], bf[8][2];
            #pragma unroll
            for (int mi = 0; mi < 2; mi++) {
                int r = wm * 32 + mi * 16 + gID;
                af[mi][0] = __float_as_uint(As[r * ROWF + kk + tig]);
                af[mi][1] = __float_as_uint(As[(r + 8) * ROWF + kk + tig]);
                af[mi][2] = __float_as_uint(As[r * ROWF + kk + tig + 4]);
                af[mi][3] = __float_as_uint(As[(r + 8) * ROWF + kk + tig + 4]);
            }
            #pragma unroll
            for (int ni = 0; ni < 8; ni++) {
                int n = wn * 64 + ni * 8 + gID;
                bf[ni][0] = __float_as_uint(Bs[n * ROWF + kk + tig]);
                bf[ni][1] = __float_as_uint(Bs[n * ROWF + kk + tig + 4]);
            }
            #pragma unroll
            for (int mi = 0; mi < 2; mi++)
                #pragma unroll
                for (int ni = 0; ni < 8; ni++)
                    mma_tf32(acc[mi][ni], af[mi], bf[ni]);
        }
        __syncthreads();
    }

    // epilogue: D fragment (gID,tig*2 / +8) per 16x8 tile
    #pragma unroll
    for (int mi = 0; mi < 2; mi++) {
        float* p0 = g_emb + (size_t)(bm + wm * 32 + mi * 16 + gID) * DM
                          + bn + wn * 64 + tig * 2;
        float* p1 = p0 + (size_t)8 * DM;
        #pragma unroll
        for (int ni = 0; ni < 8; ni++) {
            *(float2*)(p0 + ni * 8) = make_float2(acc[mi][ni][0], acc[mi][ni][1]);
            *(float2*)(p1 + ni * 8) = make_float2(acc[mi][ni][2], acc[mi][ni][3]);
        }
    }
}

// ---------------------------------------------------------------------------
// Kernel 4: gated bias + LayerNorm over DM=1024
// ---------------------------------------------------------------------------
__global__ __launch_bounds__(256) void ln_kernel(const int* __restrict__ np,
                                                 const float* __restrict__ bias,
                                                 const float* __restrict__ gamma,
                                                 const float* __restrict__ beta,
                                                 float* __restrict__ out) {
    int row = blockIdx.x;
    int t = threadIdx.x;
    float bscale = (np[row] > 0) ? 1.0f : 0.0f;

    float4 x = ((const float4*)(g_emb + (size_t)row * DM))[t];
    float4 bb = ((const float4*)bias)[t];
    x.x += bscale * bb.x; x.y += bscale * bb.y;
    x.z += bscale * bb.z; x.w += bscale * bb.w;

    float s  = x.x + x.y + x.z + x.w;
    float sq = x.x*x.x + x.y*x.y + x.z*x.z + x.w*x.w;
    #pragma unroll
    for (int o = 16; o > 0; o >>= 1) {
        s  += __shfl_xor_sync(0xffffffffu, s, o);
        sq += __shfl_xor_sync(0xffffffffu, sq, o);
    }
    __shared__ float red_s[8], red_q[8];
    int warp = t >> 5, lane = t & 31;
    if (lane == 0) { red_s[warp] = s; red_q[warp] = sq; }
    __syncthreads();
    s = 0.f; sq = 0.f;
    #pragma unroll
    for (int w = 0; w < 8; ++w) { s += red_s[w]; sq += red_q[w]; }

    float mean = s * (1.0f / DM);
    float var  = sq * (1.0f / DM) - mean * mean;
    float rstd = rsqrtf(var + EPSL);

    float4 g  = ((const float4*)gamma)[t];
    float4 be = ((const float4*)beta)[t];
    float4 o;
    o.x = (x.x - mean) * rstd * g.x + be.x;
    o.y = (x.y - mean) * rstd * g.y + be.y;
    o.z = (x.z - mean) * rstd * g.z + be.z;
    o.w = (x.w - mean) * rstd * g.w + be.w;
    ((float4*)out)[(size_t)row * (DM/4) + t] = o;
}

// ---------------------------------------------------------------------------
extern "C" void kernel_launch(void* const* d_in, const int* in_sizes, int n_in,
                              void* d_out, int out_size) {
    const float* pv    = (const float*)d_in[0];
    const int*   np    = (const int*)d_in[1];
    const float* W     = (const float*)d_in[2];
    const float* bias  = (const float*)d_in[3];
    const float* gamma = (const float*)d_in[4];
    const float* beta  = (const float*)d_in[5];
    float* out = (float*)d_out;

    cudaFuncSetAttribute(gemm_mma_kernel,
                         cudaFuncAttributeMaxDynamicSharedMemorySize, SMEM_TOTAL);

    pool_kernel<<<NPOS, 192>>>(pv, np);
    transpose_kernel<<<dim3(DM/32, DIN/32), 256>>>(W);
    gemm_mma_kernel<<<dim3(DM/BN, NPOS/BM), 256, SMEM_TOTAL>>>();
    ln_kernel<<<NPOS, 256>>>(np, bias, gamma, beta, out);
}

// round 6
// speedup vs baseline: 3.2712x; 1.2811x over previous
#include <cuda_runtime.h>
#include <cuda_fp16.h>
#include <cstdint>

#define BD   8
#define SD   512
#define PD   8
#define DIN  768
#define DM   1024
#define NPOS (BD*SD)
#define EPSL 1e-5f

// ---------------- GEMM tiling ----------------
#define BM 128
#define BN 128
#define BK 64                    // halfs (128 bytes)
#define KITERS (DIN/BK)          // 12
#define ROWB 144                 // padded row bytes (64*2 + 16)
#define A_BYTES (BM*ROWB)        // 18432
#define STAGE_BYTES (2*A_BYTES)  // 36864 (A then B)
#define SMEM_TOTAL (2*STAGE_BYTES) // 73728

// Scratch (static device memory — no allocations anywhere)
__device__ __half g_pooled[(size_t)NPOS * DIN];  // 6.3 MB (fp16-rounded)
__device__ __half g_Wt[(size_t)DM * DIN];        // 1.5 MB (W^T, K-major, fp16)
__device__ float  g_emb[(size_t)NPOS * DM];      // 16.8 MB

__device__ __forceinline__ uint32_t smem_u32(const void* p) {
    uint32_t a;
    asm("{ .reg .u64 t; cvta.to.shared.u64 t, %1; cvt.u32.u64 %0, t; }" : "=r"(a) : "l"(p));
    return a;
}

#define CP16(dst, src) \
    asm volatile("cp.async.cg.shared.global [%0], [%1], 16;" :: "r"(dst), "l"(src))
#define CP_COMMIT() asm volatile("cp.async.commit_group;" ::: "memory")
#define CP_WAIT1()  asm volatile("cp.async.wait_group 1;" ::: "memory")
#define CP_WAIT0()  asm volatile("cp.async.wait_group 0;" ::: "memory")

#define LDSM4(r, addr) \
    asm volatile("ldmatrix.sync.aligned.m8n8.x4.shared.b16 {%0,%1,%2,%3}, [%4];" \
        : "=r"((r)[0]), "=r"((r)[1]), "=r"((r)[2]), "=r"((r)[3]) : "r"(addr))

__device__ __forceinline__ void mma_f16(float* d, const uint32_t* a,
                                        uint32_t b0, uint32_t b1) {
    asm volatile("mma.sync.aligned.m16n8k16.row.col.f32.f16.f16.f32 "
        "{%0,%1,%2,%3}, {%4,%5,%6,%7}, {%8,%9}, {%0,%1,%2,%3};"
        : "+f"(d[0]), "+f"(d[1]), "+f"(d[2]), "+f"(d[3])
        : "r"(a[0]), "r"(a[1]), "r"(a[2]), "r"(a[3]), "r"(b0), "r"(b1));
}

// ---------------------------------------------------------------------------
// Kernel 1: masked mean-pool; 4-way unrolled; fp16 output.
// ---------------------------------------------------------------------------
__global__ __launch_bounds__(192) void pool_kernel(const float* __restrict__ pv,
                                                   const int* __restrict__ np) {
    int pos = blockIdx.x;
    int n = np[pos];
    float inv = (n > 0) ? 1.0f / (float)n : 0.0f;
    const float4* base = (const float4*)(pv + (size_t)pos * PD * DIN);
    int c = threadIdx.x;
    float4 a0 = make_float4(0.f,0.f,0.f,0.f), a1 = a0, a2 = a0, a3 = a0;
    int p = 0;
    for (; p + 4 <= n; p += 4) {
        float4 v0 = base[(p  ) * (DIN/4) + c];
        float4 v1 = base[(p+1) * (DIN/4) + c];
        float4 v2 = base[(p+2) * (DIN/4) + c];
        float4 v3 = base[(p+3) * (DIN/4) + c];
        a0.x+=v0.x; a0.y+=v0.y; a0.z+=v0.z; a0.w+=v0.w;
        a1.x+=v1.x; a1.y+=v1.y; a1.z+=v1.z; a1.w+=v1.w;
        a2.x+=v2.x; a2.y+=v2.y; a2.z+=v2.z; a2.w+=v2.w;
        a3.x+=v3.x; a3.y+=v3.y; a3.z+=v3.z; a3.w+=v3.w;
    }
    for (; p < n; ++p) {
        float4 v = base[p * (DIN/4) + c];
        a0.x+=v.x; a0.y+=v.y; a0.z+=v.z; a0.w+=v.w;
    }
    float rx = (a0.x+a1.x+a2.x+a3.x)*inv, ry = (a0.y+a1.y+a2.y+a3.y)*inv;
    float rz = (a0.z+a1.z+a2.z+a3.z)*inv, rw = (a0.w+a1.w+a2.w+a3.w)*inv;
    __half2* o = (__half2*)(g_pooled + (size_t)pos * DIN) + c * 2;
    o[0] = __floats2half2_rn(rx, ry);
    o[1] = __floats2half2_rn(rz, rw);
}

// ---------------------------------------------------------------------------
// Kernel 2: transpose W [768,1024] -> g_Wt [1024,768] fp16 (K-major B)
// ---------------------------------------------------------------------------
__global__ __launch_bounds__(256) void transpose_kernel(const float* __restrict__ W) {
    __shared__ float t[32][33];
    int bx = blockIdx.x, by = blockIdx.y;
    int tx = threadIdx.x & 31, ty = threadIdx.x >> 5;   // 32 x 8
    #pragma unroll
    for (int i = 0; i < 32; i += 8)
        t[ty + i][tx] = W[(size_t)(by*32 + ty + i) * DM + bx*32 + tx];
    __syncthreads();
    #pragma unroll
    for (int i = 0; i < 32; i += 8)
        g_Wt[(size_t)(bx*32 + ty + i) * DIN + by*32 + tx] = __float2half_rn(t[tx][ty + i]);
}

// ---------------------------------------------------------------------------
// Kernel 3: fp16 mma.sync GEMM  g_emb[4096,1024] = g_pooled @ g_Wt^T
// 128x128x64 tiles, cp.async double-buffer, ldmatrix frags,
// 8 warps (4x2) each computing a 32x64 warp tile. fp32 accumulate.
// ---------------------------------------------------------------------------
__global__ __launch_bounds__(256, 2) void gemm_mma_kernel() {
    extern __shared__ char smem[];
    const uint32_t sb = smem_u32(smem);
    const int tid  = threadIdx.x;
    const int wid  = tid >> 5;
    const int lane = tid & 31;
    const int gID  = lane >> 2;       // 0..7
    const int tig  = lane & 3;        // 0..3
    const int wm   = wid & 3;         // m-group: 32 rows
    const int wn   = wid >> 2;        // n-group: 64 cols
    const int bm   = blockIdx.y * BM;
    const int bn   = blockIdx.x * BN;

    // GMEM->SMEM: thread owns 4 consecutive 16B chunks (64B contiguous gmem)
    const int t4   = tid * 4;
    const int arow = t4 >> 3;         // 0..127
    const int ach  = t4 & 7;          // 0 or 4
    const __half* gA = g_pooled + (size_t)(bm + arow) * DIN + ach * 8;
    const __half* gB = g_Wt    + (size_t)(bn + arow) * DIN + ach * 8;
    const uint32_t dA = sb + arow * ROWB + ach * 16;
    const uint32_t dB = dA + (uint32_t)A_BYTES;

    // ldmatrix lane address bases (stage offset added per iter)
    const uint32_t aoff = sb + (uint32_t)((wm*32 + (lane & 15)) * ROWB
                                          + ((lane >> 4) & 1) * 16);
    const uint32_t boff = sb + (uint32_t)A_BYTES
        + (uint32_t)((wn*64 + ((lane >> 4) & 1) * 8 + (lane & 7)) * ROWB
                     + ((lane >> 3) & 1) * 16);

    float acc[2][8][4];
    #pragma unroll
    for (int mi = 0; mi < 2; mi++)
        #pragma unroll
        for (int ni = 0; ni < 8; ni++)
            #pragma unroll
            for (int q = 0; q < 4; q++) acc[mi][ni][q] = 0.f;

    // prologue: stage 0
    #pragma unroll
    for (int j = 0; j < 4; j++) {
        CP16(dA + j * 16, gA + j * 8);
        CP16(dB + j * 16, gB + j * 8);
    }
    CP_COMMIT();

    #pragma unroll 1
    for (int c = 0; c < KITERS; ++c) {
        if (c + 1 < KITERS) {
            const uint32_t st = ((c + 1) & 1) * STAGE_BYTES;
            const int k0 = (c + 1) * BK;
            #pragma unroll
            for (int j = 0; j < 4; j++) {
                CP16(dA + st + j * 16, gA + k0 + j * 8);
                CP16(dB + st + j * 16, gB + k0 + j * 8);
            }
            CP_COMMIT();
            CP_WAIT1();
        } else {
            CP_WAIT0();
        }
        __syncthreads();

        const uint32_t st = (c & 1) * STAGE_BYTES;
        #pragma unroll
        for (int ks = 0; ks < 4; ++ks) {
            const uint32_t kb = ks * 32;          // 16 halfs = 32 bytes
            uint32_t af[2][4];
            LDSM4(af[0], aoff + st + kb);
            LDSM4(af[1], aoff + st + kb + 16 * ROWB);
            uint32_t bf[4][4];                    // [nip][b0 ni, b1 ni, b0 ni+1, b1 ni+1]
            #pragma unroll
            for (int nip = 0; nip < 4; nip++)
                LDSM4(bf[nip], boff + st + kb + nip * 16 * ROWB);
            #pragma unroll
            for (int mi = 0; mi < 2; mi++)
                #pragma unroll
                for (int ni = 0; ni < 8; ni++)
                    mma_f16(acc[mi][ni], af[mi],
                            bf[ni >> 1][(ni & 1) * 2], bf[ni >> 1][(ni & 1) * 2 + 1]);
        }
        __syncthreads();
    }

    // epilogue
    #pragma unroll
    for (int mi = 0; mi < 2; mi++) {
        float* p0 = g_emb + (size_t)(bm + wm*32 + mi*16 + gID) * DM
                          + bn + wn*64 + tig*2;
        float* p1 = p0 + (size_t)8 * DM;
        #pragma unroll
        for (int ni = 0; ni < 8; ni++) {
            *(float2*)(p0 + ni*8) = make_float2(acc[mi][ni][0], acc[mi][ni][1]);
            *(float2*)(p1 + ni*8) = make_float2(acc[mi][ni][2], acc[mi][ni][3]);
        }
    }
}

// ---------------------------------------------------------------------------
// Kernel 4: gated bias + LayerNorm over DM=1024
// ---------------------------------------------------------------------------
__global__ __launch_bounds__(256) void ln_kernel(const int* __restrict__ np,
                                                 const float* __restrict__ bias,
                                                 const float* __restrict__ gamma,
                                                 const float* __restrict__ beta,
                                                 float* __restrict__ out) {
    int row = blockIdx.x;
    int t = threadIdx.x;
    float bscale = (np[row] > 0) ? 1.0f : 0.0f;

    float4 x = ((const float4*)(g_emb + (size_t)row * DM))[t];
    float4 bb = ((const float4*)bias)[t];
    x.x += bscale * bb.x; x.y += bscale * bb.y;
    x.z += bscale * bb.z; x.w += bscale * bb.w;

    float s  = x.x + x.y + x.z + x.w;
    float sq = x.x*x.x + x.y*x.y + x.z*x.z + x.w*x.w;
    #pragma unroll
    for (int o = 16; o > 0; o >>= 1) {
        s  += __shfl_xor_sync(0xffffffffu, s, o);
        sq += __shfl_xor_sync(0xffffffffu, sq, o);
    }
    __shared__ float red_s[8], red_q[8];
    int warp = t >> 5, lane = t & 31;
    if (lane == 0) { red_s[warp] = s; red_q[warp] = sq; }
    __syncthreads();
    s = 0.f; sq = 0.f;
    #pragma unroll
    for (int w = 0; w < 8; ++w) { s += red_s[w]; sq += red_q[w]; }

    float mean = s * (1.0f / DM);
    float var  = sq * (1.0f / DM) - mean * mean;
    float rstd = rsqrtf(var + EPSL);

    float4 g  = ((const float4*)gamma)[t];
    float4 be = ((const float4*)beta)[t];
    float4 o;
    o.x = (x.x - mean) * rstd * g.x + be.x;
    o.y = (x.y - mean) * rstd * g.y + be.y;
    o.z = (x.z - mean) * rstd * g.z + be.z;
    o.w = (x.w - mean) * rstd * g.w + be.w;
    ((float4*)out)[(size_t)row * (DM/4) + t] = o;
}

// ---------------------------------------------------------------------------
extern "C" void kernel_launch(void* const* d_in, const int* in_sizes, int n_in,
                              void* d_out, int out_size) {
    const float* pv    = (const float*)d_in[0];
    const int*   np    = (const int*)d_in[1];
    const float* W     = (const float*)d_in[2];
    const float* bias  = (const float*)d_in[3];
    const float* gamma = (const float*)d_in[4];
    const float* beta  = (const float*)d_in[5];
    float* out = (float*)d_out;

    cudaFuncSetAttribute(gemm_mma_kernel,
                         cudaFuncAttributeMaxDynamicSharedMemorySize, SMEM_TOTAL);

    pool_kernel<<<NPOS, 192>>>(pv, np);
    transpose_kernel<<<dim3(DM/32, DIN/32), 256>>>(W);
    gemm_mma_kernel<<<dim3(DM/BN, NPOS/BM), 256, SMEM_TOTAL>>>();
    ln_kernel<<<NPOS, 256>>>(np, bias, gamma, beta, out);
}

// round 8
// speedup vs baseline: 3.5480x; 1.0846x over previous
#include <cuda_runtime.h>
#include <cuda_fp16.h>
#include <cstdint>

#define BD   8
#define SD   512
#define PD   8
#define DIN  768
#define DM   1024
#define NPOS (BD*SD)
#define EPSL 1e-5f

// ---------------- GEMM tiling ----------------
#define BM 128
#define BN 128
#define BK 64                    // halfs (128 bytes)
#define KITERS (DIN/BK)          // 12
#define ROWB 144                 // padded row bytes
#define A_BYTES (BM*ROWB)        // 18432
#define STAGE_BYTES (2*A_BYTES)  // 36864
#define STATS_OFF   (2*STAGE_BYTES)            // 73728
// stats region: s_red[2][128], q_red[2][128], cta_s[128], cta_q[128], mean[128], rstd[128]
#define SRED_OFF   (STATS_OFF)
#define QRED_OFF   (STATS_OFF + 1024)
#define CTAS_OFF   (STATS_OFF + 2048)
#define CTAQ_OFF   (STATS_OFF + 2560)
#define MEAN_OFF   (STATS_OFF + 3072)
#define RSTD_OFF   (STATS_OFF + 3584)
#define SMEM_TOTAL (STATS_OFF + 4096)          // 77824

#define NCLUSTER 8               // DM/BN CTAs own one full row block

// Scratch
__device__ __half g_pooled[(size_t)NPOS * DIN];  // 6.3 MB
__device__ __half g_Wt[(size_t)DM * DIN];        // 1.5 MB (W^T, K-major)

__device__ __forceinline__ uint32_t smem_u32(const void* p) {
    uint32_t a;
    asm("{ .reg .u64 t; cvta.to.shared.u64 t, %1; cvt.u32.u64 %0, t; }" : "=r"(a) : "l"(p));
    return a;
}
__device__ __forceinline__ uint32_t mapa_u32(uint32_t addr, uint32_t rank) {
    uint32_t r;
    asm("mapa.shared::cluster.u32 %0, %1, %2;" : "=r"(r) : "r"(addr), "r"(rank));
    return r;
}
__device__ __forceinline__ float ld_dsm(uint32_t addr) {
    float v;
    asm volatile("ld.shared::cluster.f32 %0, [%1];" : "=f"(v) : "r"(addr));
    return v;
}
#define CLUSTER_SYNC() do { \
    asm volatile("barrier.cluster.arrive.aligned;" ::: "memory"); \
    asm volatile("barrier.cluster.wait.aligned;" ::: "memory"); } while (0)

#define CP16(dst, src) \
    asm volatile("cp.async.cg.shared.global [%0], [%1], 16;" :: "r"(dst), "l"(src))
#define CP_COMMIT() asm volatile("cp.async.commit_group;" ::: "memory")
#define CP_WAIT1()  asm volatile("cp.async.wait_group 1;" ::: "memory")
#define CP_WAIT0()  asm volatile("cp.async.wait_group 0;" ::: "memory")

#define LDSM4(r, addr) \
    asm volatile("ldmatrix.sync.aligned.m8n8.x4.shared.b16 {%0,%1,%2,%3}, [%4];" \
        : "=r"((r)[0]), "=r"((r)[1]), "=r"((r)[2]), "=r"((r)[3]) : "r"(addr))

__device__ __forceinline__ void mma_f16(float* d, const uint32_t* a,
                                        uint32_t b0, uint32_t b1) {
    asm volatile("mma.sync.aligned.m16n8k16.row.col.f32.f16.f16.f32 "
        "{%0,%1,%2,%3}, {%4,%5,%6,%7}, {%8,%9}, {%0,%1,%2,%3};"
        : "+f"(d[0]), "+f"(d[1]), "+f"(d[2]), "+f"(d[3])
        : "r"(a[0]), "r"(a[1]), "r"(a[2]), "r"(a[3]), "r"(b0), "r"(b1));
}

// ---------------------------------------------------------------------------
// Kernel 1: fused prep — blocks [0,4096): mean-pool; [4096,4864): W transpose.
// ---------------------------------------------------------------------------
__global__ __launch_bounds__(256) void prep_kernel(const float* __restrict__ pv,
                                                   const int* __restrict__ np,
                                                   const float* __restrict__ W) {
    int bid = blockIdx.x;
    if (bid < NPOS) {
        if (threadIdx.x >= 192) return;
        int n = np[bid];
        float inv = (n > 0) ? 1.0f / (float)n : 0.0f;
        const float4* base = (const float4*)(pv + (size_t)bid * PD * DIN);
        int c = threadIdx.x;
        float4 a0 = make_float4(0.f,0.f,0.f,0.f), a1 = a0, a2 = a0, a3 = a0;
        int p = 0;
        for (; p + 4 <= n; p += 4) {
            float4 v0 = base[(p  ) * (DIN/4) + c];
            float4 v1 = base[(p+1) * (DIN/4) + c];
            float4 v2 = base[(p+2) * (DIN/4) + c];
            float4 v3 = base[(p+3) * (DIN/4) + c];
            a0.x+=v0.x; a0.y+=v0.y; a0.z+=v0.z; a0.w+=v0.w;
            a1.x+=v1.x; a1.y+=v1.y; a1.z+=v1.z; a1.w+=v1.w;
            a2.x+=v2.x; a2.y+=v2.y; a2.z+=v2.z; a2.w+=v2.w;
            a3.x+=v3.x; a3.y+=v3.y; a3.z+=v3.z; a3.w+=v3.w;
        }
        for (; p < n; ++p) {
            float4 v = base[p * (DIN/4) + c];
            a0.x+=v.x; a0.y+=v.y; a0.z+=v.z; a0.w+=v.w;
        }
        float rx = (a0.x+a1.x+a2.x+a3.x)*inv, ry = (a0.y+a1.y+a2.y+a3.y)*inv;
        float rz = (a0.z+a1.z+a2.z+a3.z)*inv, rw = (a0.w+a1.w+a2.w+a3.w)*inv;
        __half2* o = (__half2*)(g_pooled + (size_t)bid * DIN) + c * 2;
        o[0] = __floats2half2_rn(rx, ry);
        o[1] = __floats2half2_rn(rz, rw);
    } else {
        __shared__ float t[32][33];
        int b = bid - NPOS;                    // 0..767
        int bx = b & 31, by = b >> 5;          // DM/32=32 cols, DIN/32=24 rows
        int tx = threadIdx.x & 31, ty = threadIdx.x >> 5;
        #pragma unroll
        for (int i = 0; i < 32; i += 8)
            t[ty + i][tx] = W[(size_t)(by*32 + ty + i) * DM + bx*32 + tx];
        __syncthreads();
        #pragma unroll
        for (int i = 0; i < 32; i += 8)
            g_Wt[(size_t)(bx*32 + ty + i) * DIN + by*32 + tx] = __float2half_rn(t[tx][ty + i]);
    }
}

// ---------------------------------------------------------------------------
// Kernel 2: fp16 mma GEMM + fused bias + LayerNorm (8-CTA cluster along N).
// out[4096,1024] = LN( pooled @ Wt^T + gated bias ) * gamma + beta
// ---------------------------------------------------------------------------
__global__ __launch_bounds__(256, 2) __cluster_dims__(NCLUSTER, 1, 1)
void gemm_ln_kernel(const int* __restrict__ np,
                    const float* __restrict__ bias,
                    const float* __restrict__ gamma,
                    const float* __restrict__ beta,
                    float* __restrict__ out) {
    extern __shared__ char smem[];
    const uint32_t sb = smem_u32(smem);
    const int tid  = threadIdx.x;
    const int wid  = tid >> 5;
    const int lane = tid & 31;
    const int gID  = lane >> 2;
    const int tig  = lane & 3;
    const int wm   = wid & 3;
    const int wn   = wid >> 2;
    const int bm   = blockIdx.y * BM;
    const int bn   = blockIdx.x * BN;

    const int t4   = tid * 4;
    const int arow = t4 >> 3;
    const int ach  = t4 & 7;
    const __half* gA = g_pooled + (size_t)(bm + arow) * DIN + ach * 8;
    const __half* gB = g_Wt    + (size_t)(bn + arow) * DIN + ach * 8;
    const uint32_t dA = sb + arow * ROWB + ach * 16;
    const uint32_t dB = dA + (uint32_t)A_BYTES;

    const uint32_t aoff = sb + (uint32_t)((wm*32 + (lane & 15)) * ROWB
                                          + ((lane >> 4) & 1) * 16);
    const uint32_t boff = sb + (uint32_t)A_BYTES
        + (uint32_t)((wn*64 + ((lane >> 4) & 1) * 8 + (lane & 7)) * ROWB
                     + ((lane >> 3) & 1) * 16);

    float acc[2][8][4];
    #pragma unroll
    for (int mi = 0; mi < 2; mi++)
        #pragma unroll
        for (int ni = 0; ni < 8; ni++)
            #pragma unroll
            for (int q = 0; q < 4; q++) acc[mi][ni][q] = 0.f;

    #pragma unroll
    for (int j = 0; j < 4; j++) {
        CP16(dA + j * 16, gA + j * 8);
        CP16(dB + j * 16, gB + j * 8);
    }
    CP_COMMIT();

    #pragma unroll 1
    for (int c = 0; c < KITERS; ++c) {
        if (c + 1 < KITERS) {
            const uint32_t st = ((c + 1) & 1) * STAGE_BYTES;
            const int k0 = (c + 1) * BK;
            #pragma unroll
            for (int j = 0; j < 4; j++) {
                CP16(dA + st + j * 16, gA + k0 + j * 8);
                CP16(dB + st + j * 16, gB + k0 + j * 8);
            }
            CP_COMMIT();
            CP_WAIT1();
        } else {
            CP_WAIT0();
        }
        __syncthreads();

        const uint32_t st = (c & 1) * STAGE_BYTES;
        #pragma unroll
        for (int ks = 0; ks < 4; ++ks) {
            const uint32_t kb = ks * 32;
            uint32_t af[2][4];
            LDSM4(af[0], aoff + st + kb);
            LDSM4(af[1], aoff + st + kb + 16 * ROWB);
            uint32_t bf[4][4];
            #pragma unroll
            for (int nip = 0; nip < 4; nip++)
                LDSM4(bf[nip], boff + st + kb + nip * 16 * ROWB);
            #pragma unroll
            for (int mi = 0; mi < 2; mi++)
                #pragma unroll
                for (int ni = 0; ni < 8; ni++)
                    mma_f16(acc[mi][ni], af[mi],
                            bf[ni >> 1][(ni & 1) * 2], bf[ni >> 1][(ni & 1) * 2 + 1]);
        }
        __syncthreads();
    }

    // ---------------- fused epilogue: bias + LN ----------------
    // thread's 4 rows: wm*32 + mi*16 + h*8 + gID   (mi,h in {0,1})
    // thread's cols (within wn's 64): ni*8 + tig*2 + {0,1}
    const int ncol = bn + wn * 64 + tig * 2;

    float bs[2][2];
    #pragma unroll
    for (int mi = 0; mi < 2; mi++)
        #pragma unroll
        for (int h = 0; h < 2; h++)
            bs[mi][h] = (np[bm + wm*32 + mi*16 + h*8 + gID] > 0) ? 1.0f : 0.0f;

    float2 b2[8];
    #pragma unroll
    for (int ni = 0; ni < 8; ni++) b2[ni] = *(const float2*)(bias + ncol + ni * 8);

    float ps[4] = {0.f, 0.f, 0.f, 0.f}, pq[4] = {0.f, 0.f, 0.f, 0.f};
    #pragma unroll
    for (int mi = 0; mi < 2; mi++)
        #pragma unroll
        for (int ni = 0; ni < 8; ni++) {
            acc[mi][ni][0] += bs[mi][0] * b2[ni].x;
            acc[mi][ni][1] += bs[mi][0] * b2[ni].y;
            acc[mi][ni][2] += bs[mi][1] * b2[ni].x;
            acc[mi][ni][3] += bs[mi][1] * b2[ni].y;
            ps[mi*2+0] += acc[mi][ni][0] + acc[mi][ni][1];
            ps[mi*2+1] += acc[mi][ni][2] + acc[mi][ni][3];
            pq[mi*2+0] += acc[mi][ni][0]*acc[mi][ni][0] + acc[mi][ni][1]*acc[mi][ni][1];
            pq[mi*2+1] += acc[mi][ni][2]*acc[mi][ni][2] + acc[mi][ni][3]*acc[mi][ni][3];
        }
    // reduce over the 4 lanes of the quad (bits 0-1 of lane)
    #pragma unroll
    for (int o = 1; o <= 2; o <<= 1)
        #pragma unroll
        for (int i = 0; i < 4; i++) {
            ps[i] += __shfl_xor_sync(0xffffffffu, ps[i], o);
            pq[i] += __shfl_xor_sync(0xffffffffu, pq[i], o);
        }
    if (tig == 0) {
        #pragma unroll
        for (int i = 0; i < 4; i++) {
            int r = wm*32 + (i >> 1)*16 + (i & 1)*8 + gID;
            *(float*)(smem + SRED_OFF + (wn*128 + r)*4) = ps[i];
            *(float*)(smem + QRED_OFF + (wn*128 + r)*4) = pq[i];
        }
    }
    __syncthreads();
    if (tid < 128) {
        float s = *(float*)(smem + SRED_OFF + tid*4) + *(float*)(smem + SRED_OFF + (128+tid)*4);
        float q = *(float*)(smem + QRED_OFF + tid*4) + *(float*)(smem + QRED_OFF + (128+tid)*4);
        *(float*)(smem + CTAS_OFF + tid*4) = s;
        *(float*)(smem + CTAQ_OFF + tid*4) = q;
    }
    __syncthreads();
    CLUSTER_SYNC();

    if (tid < 128) {
        float s = 0.f, q = 0.f;
        #pragma unroll
        for (uint32_t rk = 0; rk < NCLUSTER; rk++) {
            s += ld_dsm(mapa_u32(sb + CTAS_OFF + tid*4, rk));
            q += ld_dsm(mapa_u32(sb + CTAQ_OFF + tid*4, rk));
        }
        float mean = s * (1.0f / DM);
        float var  = q * (1.0f / DM) - mean * mean;
        *(float*)(smem + MEAN_OFF + tid*4) = mean;
        *(float*)(smem + RSTD_OFF + tid*4) = rsqrtf(var + EPSL);
    }
    __syncthreads();

    float2 g2[8], be2[8];
    #pragma unroll
    for (int ni = 0; ni < 8; ni++) {
        g2[ni]  = *(const float2*)(gamma + ncol + ni * 8);
        be2[ni] = *(const float2*)(beta  + ncol + ni * 8);
    }
    #pragma unroll
    for (int mi = 0; mi < 2; mi++)
        #pragma unroll
        for (int h = 0; h < 2; h++) {
            int r = wm*32 + mi*16 + h*8 + gID;
            float mean = *(float*)(smem + MEAN_OFF + r*4);
            float rstd = *(float*)(smem + RSTD_OFF + r*4);
            float* prow = out + (size_t)(bm + r) * DM + ncol;
            #pragma unroll
            for (int ni = 0; ni < 8; ni++) {
                float x0 = acc[mi][ni][h*2+0], x1 = acc[mi][ni][h*2+1];
                float2 v = make_float2((x0 - mean) * rstd * g2[ni].x + be2[ni].x,
                                       (x1 - mean) * rstd * g2[ni].y + be2[ni].y);
                *(float2*)(prow + ni * 8) = v;
            }
        }

    CLUSTER_SYNC();   // no CTA exits while peers may still read its stats
}

// ---------------------------------------------------------------------------
extern "C" void kernel_launch(void* const* d_in, const int* in_sizes, int n_in,
                              void* d_out, int out_size) {
    const float* pv    = (const float*)d_in[0];
    const int*   np    = (const int*)d_in[1];
    const float* W     = (const float*)d_in[2];
    const float* bias  = (const float*)d_in[3];
    const float* gamma = (const float*)d_in[4];
    const float* beta  = (const float*)d_in[5];
    float* out = (float*)d_out;

    cudaFuncSetAttribute(gemm_ln_kernel,
                         cudaFuncAttributeMaxDynamicSharedMemorySize, SMEM_TOTAL);

    prep_kernel<<<NPOS + (DM/32)*(DIN/32), 256>>>(pv, np, W);
    gemm_ln_kernel<<<dim3(DM/BN, NPOS/BM), 256, SMEM_TOTAL>>>(np, bias, gamma, beta, out);
}

// round 10
// speedup vs baseline: 3.8433x; 1.0832x over previous
#include <cuda_runtime.h>
#include <cuda_fp16.h>
#include <cstdint>

#define BD   8
#define SD   512
#define PD   8
#define DIN  768
#define DM   1024
#define NPOS (BD*SD)
#define EPSL 1e-5f

// ---------------- GEMM tiling ----------------
#define BM 64
#define BN 128
#define BK 64                    // halfs (128 bytes)
#define KITERS (DIN/BK)          // 12
#define ROWB 144                 // padded row bytes
#define A_BYTES (BM*ROWB)        // 9216
#define B_BYTES (BN*ROWB)        // 18432
#define STAGE_BYTES (A_BYTES + B_BYTES)   // 27648
#define STATS_OFF   (2*STAGE_BYTES)       // 55296
// stats region (BM=64 rows): s_red[2][64], q_red[2][64], cta_s[64], cta_q[64], mean[64], rstd[64]
#define SRED_OFF   (STATS_OFF)
#define QRED_OFF   (STATS_OFF + 512)
#define CTAS_OFF   (STATS_OFF + 1024)
#define CTAQ_OFF   (STATS_OFF + 1280)
#define MEAN_OFF   (STATS_OFF + 1536)
#define RSTD_OFF   (STATS_OFF + 1792)
#define SMEM_TOTAL (STATS_OFF + 2048)     // 57344

#define NCLUSTER 8               // DM/BN CTAs own one full row block

// Scratch
__device__ __half g_pooled[(size_t)NPOS * DIN];  // 6.3 MB
__device__ __half g_Wt[(size_t)DM * DIN];        // 1.5 MB (W^T, K-major)

__device__ __forceinline__ uint32_t smem_u32(const void* p) {
    uint32_t a;
    asm("{ .reg .u64 t; cvta.to.shared.u64 t, %1; cvt.u32.u64 %0, t; }" : "=r"(a) : "l"(p));
    return a;
}
__device__ __forceinline__ uint32_t mapa_u32(uint32_t addr, uint32_t rank) {
    uint32_t r;
    asm("mapa.shared::cluster.u32 %0, %1, %2;" : "=r"(r) : "r"(addr), "r"(rank));
    return r;
}
__device__ __forceinline__ float ld_dsm(uint32_t addr) {
    float v;
    asm volatile("ld.shared::cluster.f32 %0, [%1];" : "=f"(v) : "r"(addr));
    return v;
}
#define CLUSTER_SYNC() do { \
    asm volatile("barrier.cluster.arrive.aligned;" ::: "memory"); \
    asm volatile("barrier.cluster.wait.aligned;" ::: "memory"); } while (0)

#define CP16(dst, src) \
    asm volatile("cp.async.cg.shared.global [%0], [%1], 16;" :: "r"(dst), "l"(src))
#define CP_COMMIT() asm volatile("cp.async.commit_group;" ::: "memory")
#define CP_WAIT1()  asm volatile("cp.async.wait_group 1;" ::: "memory")
#define CP_WAIT0()  asm volatile("cp.async.wait_group 0;" ::: "memory")

#define LDSM4(r, addr) \
    asm volatile("ldmatrix.sync.aligned.m8n8.x4.shared.b16 {%0,%1,%2,%3}, [%4];" \
        : "=r"((r)[0]), "=r"((r)[1]), "=r"((r)[2]), "=r"((r)[3]) : "r"(addr))

__device__ __forceinline__ void mma_f16(float* d, const uint32_t* a,
                                        uint32_t b0, uint32_t b1) {
    asm volatile("mma.sync.aligned.m16n8k16.row.col.f32.f16.f16.f32 "
        "{%0,%1,%2,%3}, {%4,%5,%6,%7}, {%8,%9}, {%0,%1,%2,%3};"
        : "+f"(d[0]), "+f"(d[1]), "+f"(d[2]), "+f"(d[3])
        : "r"(a[0]), "r"(a[1]), "r"(a[2]), "r"(a[3]), "r"(b0), "r"(b1));
}

// ---------------------------------------------------------------------------
// Kernel 1: fused prep — blocks [0,4096): mean-pool; [4096,4864): W transpose.
// ---------------------------------------------------------------------------
__global__ __launch_bounds__(256) void prep_kernel(const float* __restrict__ pv,
                                                   const int* __restrict__ np,
                                                   const float* __restrict__ W) {
    int bid = blockIdx.x;
    if (bid < NPOS) {
        if (threadIdx.x >= 192) return;
        int n = np[bid];
        float inv = (n > 0) ? 1.0f / (float)n : 0.0f;
        const float4* base = (const float4*)(pv + (size_t)bid * PD * DIN);
        int c = threadIdx.x;
        float4 a0 = make_float4(0.f,0.f,0.f,0.f), a1 = a0, a2 = a0, a3 = a0;
        int p = 0;
        for (; p + 4 <= n; p += 4) {
            float4 v0 = base[(p  ) * (DIN/4) + c];
            float4 v1 = base[(p+1) * (DIN/4) + c];
            float4 v2 = base[(p+2) * (DIN/4) + c];
            float4 v3 = base[(p+3) * (DIN/4) + c];
            a0.x+=v0.x; a0.y+=v0.y; a0.z+=v0.z; a0.w+=v0.w;
            a1.x+=v1.x; a1.y+=v1.y; a1.z+=v1.z; a1.w+=v1.w;
            a2.x+=v2.x; a2.y+=v2.y; a2.z+=v2.z; a2.w+=v2.w;
            a3.x+=v3.x; a3.y+=v3.y; a3.z+=v3.z; a3.w+=v3.w;
        }
        for (; p < n; ++p) {
            float4 v = base[p * (DIN/4) + c];
            a0.x+=v.x; a0.y+=v.y; a0.z+=v.z; a0.w+=v.w;
        }
        float rx = (a0.x+a1.x+a2.x+a3.x)*inv, ry = (a0.y+a1.y+a2.y+a3.y)*inv;
        float rz = (a0.z+a1.z+a2.z+a3.z)*inv, rw = (a0.w+a1.w+a2.w+a3.w)*inv;
        __half2* o = (__half2*)(g_pooled + (size_t)bid * DIN) + c * 2;
        o[0] = __floats2half2_rn(rx, ry);
        o[1] = __floats2half2_rn(rz, rw);
    } else {
        __shared__ float t[32][33];
        int b = bid - NPOS;                    // 0..767
        int bx = b & 31, by = b >> 5;
        int tx = threadIdx.x & 31, ty = threadIdx.x >> 5;
        #pragma unroll
        for (int i = 0; i < 32; i += 8)
            t[ty + i][tx] = W[(size_t)(by*32 + ty + i) * DM + bx*32 + tx];
        __syncthreads();
        #pragma unroll
        for (int i = 0; i < 32; i += 8)
            g_Wt[(size_t)(bx*32 + ty + i) * DIN + by*32 + tx] = __float2half_rn(t[tx][ty + i]);
    }
}

// ---------------------------------------------------------------------------
// Kernel 2: fp16 mma GEMM + fused bias + LayerNorm (8-CTA cluster along N).
// BM=64: 8 warps, each a 16x64 warp tile (wm 0..3, wn 0..1). 3 CTAs/SM target.
// ---------------------------------------------------------------------------
__global__ __launch_bounds__(256, 3) __cluster_dims__(NCLUSTER, 1, 1)
void gemm_ln_kernel(const int* __restrict__ np,
                    const float* __restrict__ bias,
                    const float* __restrict__ gamma,
                    const float* __restrict__ beta,
                    float* __restrict__ out) {
    extern __shared__ char smem[];
    const uint32_t sb = smem_u32(smem);
    const int tid  = threadIdx.x;
    const int wid  = tid >> 5;
    const int lane = tid & 31;
    const int gID  = lane >> 2;
    const int tig  = lane & 3;
    const int wm   = wid & 3;         // m-group: 16 rows
    const int wn   = wid >> 2;        // n-group: 64 cols
    const int bm   = blockIdx.y * BM;
    const int bn   = blockIdx.x * BN;

    // GMEM->SMEM loaders (chunk = 16B = 8 halfs; row = chunk>>3, col8 = chunk&7)
    const int ar0 = tid >> 3, ac0 = tid & 7;               // A: 2 chunks (j*256)
    const __half* gA = g_pooled + (size_t)(bm + ar0) * DIN + ac0 * 8;
    const __half* gB = g_Wt    + (size_t)(bn + ar0) * DIN + ac0 * 8;
    const uint32_t dA = sb + ar0 * ROWB + ac0 * 16;
    const uint32_t dB = sb + A_BYTES + ar0 * ROWB + ac0 * 16;
    // stepping by 256 chunks = 32 rows
    #define ASTEP (32*ROWB)
    #define GSTEP (32*DIN)

    const uint32_t aoff = sb + (uint32_t)((wm*16 + (lane & 15)) * ROWB
                                          + ((lane >> 4) & 1) * 16);
    const uint32_t boff = sb + (uint32_t)A_BYTES
        + (uint32_t)((wn*64 + ((lane >> 4) & 1) * 8 + (lane & 7)) * ROWB
                     + ((lane >> 3) & 1) * 16);

    float acc[8][4];
    #pragma unroll
    for (int ni = 0; ni < 8; ni++)
        #pragma unroll
        for (int q = 0; q < 4; q++) acc[ni][q] = 0.f;

    // prologue: stage 0
    #pragma unroll
    for (int j = 0; j < 2; j++) CP16(dA + j * ASTEP, gA + (size_t)j * GSTEP);
    #pragma unroll
    for (int j = 0; j < 4; j++) CP16(dB + j * ASTEP, gB + (size_t)j * GSTEP);
    CP_COMMIT();

    #pragma unroll 1
    for (int c = 0; c < KITERS; ++c) {
        if (c + 1 < KITERS) {
            const uint32_t st = ((c + 1) & 1) * STAGE_BYTES;
            const int k0 = (c + 1) * BK;
            #pragma unroll
            for (int j = 0; j < 2; j++) CP16(dA + st + j * ASTEP, gA + (size_t)j * GSTEP + k0);
            #pragma unroll
            for (int j = 0; j < 4; j++) CP16(dB + st + j * ASTEP, gB + (size_t)j * GSTEP + k0);
            CP_COMMIT();
            CP_WAIT1();
        } else {
            CP_WAIT0();
        }
        __syncthreads();

        const uint32_t st = (c & 1) * STAGE_BYTES;
        #pragma unroll
        for (int ks = 0; ks < 4; ++ks) {
            const uint32_t kb = ks * 32;
            uint32_t af[4];
            LDSM4(af, aoff + st + kb);
            uint32_t bf[4][4];
            #pragma unroll
            for (int nip = 0; nip < 4; nip++)
                LDSM4(bf[nip], boff + st + kb + nip * 16 * ROWB);
            #pragma unroll
            for (int ni = 0; ni < 8; ni++)
                mma_f16(acc[ni], af,
                        bf[ni >> 1][(ni & 1) * 2], bf[ni >> 1][(ni & 1) * 2 + 1]);
        }
        __syncthreads();
    }

    // ---------------- fused epilogue: bias + LN ----------------
    // thread rows: wm*16 + h*8 + gID (h in {0,1}); cols: wn*64 + ni*8 + tig*2
    const int ncol = bn + wn * 64 + tig * 2;

    float bs[2];
    #pragma unroll
    for (int h = 0; h < 2; h++)
        bs[h] = (np[bm + wm*16 + h*8 + gID] > 0) ? 1.0f : 0.0f;

    float2 b2[8];
    #pragma unroll
    for (int ni = 0; ni < 8; ni++) b2[ni] = *(const float2*)(bias + ncol + ni * 8);

    float ps[2] = {0.f, 0.f}, pq[2] = {0.f, 0.f};
    #pragma unroll
    for (int ni = 0; ni < 8; ni++) {
        acc[ni][0] += bs[0] * b2[ni].x;
        acc[ni][1] += bs[0] * b2[ni].y;
        acc[ni][2] += bs[1] * b2[ni].x;
        acc[ni][3] += bs[1] * b2[ni].y;
        ps[0] += acc[ni][0] + acc[ni][1];
        ps[1] += acc[ni][2] + acc[ni][3];
        pq[0] += acc[ni][0]*acc[ni][0] + acc[ni][1]*acc[ni][1];
        pq[1] += acc[ni][2]*acc[ni][2] + acc[ni][3]*acc[ni][3];
    }
    #pragma unroll
    for (int o = 1; o <= 2; o <<= 1)
        #pragma unroll
        for (int i = 0; i < 2; i++) {
            ps[i] += __shfl_xor_sync(0xffffffffu, ps[i], o);
            pq[i] += __shfl_xor_sync(0xffffffffu, pq[i], o);
        }
    if (tig == 0) {
        #pragma unroll
        for (int i = 0; i < 2; i++) {
            int r = wm*16 + i*8 + gID;
            *(float*)(smem + SRED_OFF + (wn*64 + r)*4) = ps[i];
            *(float*)(smem + QRED_OFF + (wn*64 + r)*4) = pq[i];
        }
    }
    __syncthreads();
    if (tid < 64) {
        float s = *(float*)(smem + SRED_OFF + tid*4) + *(float*)(smem + SRED_OFF + (64+tid)*4);
        float q = *(float*)(smem + QRED_OFF + tid*4) + *(float*)(smem + QRED_OFF + (64+tid)*4);
        *(float*)(smem + CTAS_OFF + tid*4) = s;
        *(float*)(smem + CTAQ_OFF + tid*4) = q;
    }
    __syncthreads();
    CLUSTER_SYNC();

    if (tid < 64) {
        float s = 0.f, q = 0.f;
        #pragma unroll
        for (uint32_t rk = 0; rk < NCLUSTER; rk++) {
            s += ld_dsm(mapa_u32(sb + CTAS_OFF + tid*4, rk));
            q += ld_dsm(mapa_u32(sb + CTAQ_OFF + tid*4, rk));
        }
        float mean = s * (1.0f / DM);
        float var  = q * (1.0f / DM) - mean * mean;
        *(float*)(smem + MEAN_OFF + tid*4) = mean;
        *(float*)(smem + RSTD_OFF + tid*4) = rsqrtf(var + EPSL);
    }
    __syncthreads();

    float2 g2[8], be2[8];
    #pragma unroll
    for (int ni = 0; ni < 8; ni++) {
        g2[ni]  = *(const float2*)(gamma + ncol + ni * 8);
        be2[ni] = *(const float2*)(beta  + ncol + ni * 8);
    }
    #pragma unroll
    for (int h = 0; h < 2; h++) {
        int r = wm*16 + h*8 + gID;
        float mean = *(float*)(smem + MEAN_OFF + r*4);
        float rstd = *(float*)(smem + RSTD_OFF + r*4);
        float* prow = out + (size_t)(bm + r) * DM + ncol;
        #pragma unroll
        for (int ni = 0; ni < 8; ni++) {
            float x0 = acc[ni][h*2+0], x1 = acc[ni][h*2+1];
            float2 v = make_float2((x0 - mean) * rstd * g2[ni].x + be2[ni].x,
                                   (x1 - mean) * rstd * g2[ni].y + be2[ni].y);
            *(float2*)(prow + ni * 8) = v;
        }
    }

    CLUSTER_SYNC();   // no CTA exits while peers may still read its stats
}

// ---------------------------------------------------------------------------
extern "C" void kernel_launch(void* const* d_in, const int* in_sizes, int n_in,
                              void* d_out, int out_size) {
    const float* pv    = (const float*)d_in[0];
    const int*   np    = (const int*)d_in[1];
    const float* W     = (const float*)d_in[2];
    const float* bias  = (const float*)d_in[3];
    const float* gamma = (const float*)d_in[4];
    const float* beta  = (const float*)d_in[5];
    float* out = (float*)d_out;

    cudaFuncSetAttribute(gemm_ln_kernel,
                         cudaFuncAttributeMaxDynamicSharedMemorySize, SMEM_TOTAL);

    prep_kernel<<<NPOS + (DM/32)*(DIN/32), 256>>>(pv, np, W);
    gemm_ln_kernel<<<dim3(DM/BN, NPOS/BM), 256, SMEM_TOTAL>>>(np, bias, gamma, beta, out);
}